// round 17
// baseline (speedup 1.0000x reference)
#include <cuda_runtime.h>
#include <cuda_bf16.h>
#include <math.h>

// ---------------------------------------------------------------------------
// NAM-LSS V2 fused kernel, v11: bf16 m16n8k16 + 1024 threads (32 warps).
// Warp grid 8m x 4n over the 128x128 tile: per-thread epilogue halves
// (16 elements), per-warp mma stream halves, occupancy 25% -> 50%.
// LN stats exchange across the 4 n-warps of each m-group via smem +
// 128-thread named barriers. Weights pre-transposed to bf16 [f][n][k] by a
// prep kernel; cp.async staging; tanh gelu; raw-bits bf16 scratch.
// ---------------------------------------------------------------------------

namespace {
constexpr int B_TOT  = 16384;
constexpr int F      = 64;
constexpr int NB     = 64;
constexpr int H1     = 128;
constexpr int H2     = 128;
constexpr int TM     = 128;
constexpr int NTHR   = 1024;   // 32 warps: 8 m-groups x 4 n-warps
constexpr float LN_EPS = 1e-5f;

// u16-unit row strides (bytes = 2x; all ==16 mod 128 bytes)
constexpr int SA_R = 72;    // rbf [128][64+pad]
constexpr int SA_H = 136;   // hbuf [128][128+pad]
constexpr int SB_1 = 72;    // W1t/Wrt [128][64+pad]
constexpr int SB_2 = 136;   // W2t [128][128+pad]

// byte offsets in dynamic smem
constexpr int B_W1T = 0;
constexpr int B_W2T = B_W1T + 128 * SB_1 * 2;
constexpr int B_WRT = B_W2T + 128 * SB_2 * 2;
constexpr int B_VEC = B_WRT + 128 * SB_1 * 2;
constexpr int B_WSM = B_VEC + 7 * 128 * 4;
constexpr int B_SCR = B_WSM + 256;
constexpr int B_LNR = B_SCR + 128 * SA_H * 2;   // float2 [128][4]
constexpr int B_HRD = B_SCR;                    // head scratch aliases SCR
constexpr int SMEM_BYTES = B_LNR + 128 * 4 * 8; // 114,432
}

__device__ __nv_bfloat16 g_w1t[F * H1 * NB];
__device__ __nv_bfloat16 g_w2t[F * H2 * H1];
__device__ __nv_bfloat16 g_wrt[F * H2 * NB];

__global__ void transpose_prep(const float* __restrict__ in,
                               __nv_bfloat16* __restrict__ outp,
                               int K, int N) {
    __shared__ float ts[128 * 65];
    int f  = blockIdx.x / (N / 64);
    int nc = blockIdx.x % (N / 64);
    const float* src = in + (size_t)f * K * N + nc * 64;
    for (int idx = threadIdx.x; idx < K * 64; idx += 256) {
        int k = idx >> 6, n = idx & 63;
        ts[k * 65 + n] = src[(size_t)k * N + n];
    }
    __syncthreads();
    unsigned* dst = (unsigned*)(outp + (size_t)f * N * K);
    int khalf = K >> 1;
    for (int idx = threadIdx.x; idx < 64 * khalf; idx += 256) {
        int n = idx / khalf, kp = idx % khalf;
        float lo = ts[(2 * kp) * 65 + n];
        float hi = ts[(2 * kp + 1) * 65 + n];
        unsigned u;
        asm("cvt.rn.bf16x2.f32 %0, %1, %2;" : "=r"(u) : "f"(hi), "f"(lo));
        dst[(size_t)(nc * 64 + n) * khalf + kp] = u;
    }
}

__device__ __forceinline__ void mma16(float* d, const unsigned* a, unsigned b0, unsigned b1) {
    asm("mma.sync.aligned.m16n8k16.row.col.f32.bf16.bf16.f32 "
        "{%0,%1,%2,%3}, {%4,%5,%6,%7}, {%8,%9}, {%0,%1,%2,%3};"
        : "+f"(d[0]), "+f"(d[1]), "+f"(d[2]), "+f"(d[3])
        : "r"(a[0]), "r"(a[1]), "r"(a[2]), "r"(a[3]), "r"(b0), "r"(b1));
}

__device__ __forceinline__ unsigned pack_bf2(float lo, float hi) {
    unsigned u;
    asm("cvt.rn.bf16x2.f32 %0, %1, %2;" : "=r"(u) : "f"(hi), "f"(lo));
    return u;
}

__device__ __forceinline__ void cp16(unsigned dst, const void* src) {
    asm volatile("cp.async.cg.shared.global [%0], [%1], 16;" :: "r"(dst), "l"(src));
}

__device__ __forceinline__ float qred(float v) {
    v += __shfl_xor_sync(0xffffffffu, v, 1);
    v += __shfl_xor_sync(0xffffffffu, v, 2);
    return v;
}

__device__ __forceinline__ float gelu_fast(float v) {
    float z = 0.7978845608028654f * fmaf(0.044715f * v, v * v, v);
    float t;
    asm("tanh.approx.f32 %0, %1;" : "=f"(t) : "f"(z));
    return 0.5f * v * (1.0f + t);
}

__device__ __forceinline__ float softplus_f(float v) {
    return (v > 20.0f) ? v : log1pf(expf(v));
}

__device__ __forceinline__ float clipf(float v, float lo, float hi) {
    return fminf(fmaxf(v, lo), hi);
}

// acc[4][4] += A[16 x 16K] @ B^T (cols ncol0..+31); bf16 smem (u16 ptrs)
__device__ __forceinline__ void gemm16(float acc[4][4],
                                       const unsigned short* A, int sa,
                                       const unsigned short* B, int sb,
                                       int ksteps, int mrow0, int ncol0,
                                       int gid, int tidg) {
    for (int s = 0; s < ksteps; ++s) {
        int k0 = 16 * s + 2 * tidg;
        unsigned a[4];
        a[0] = *(const unsigned*)(A + (mrow0 + gid) * sa + k0);
        a[1] = *(const unsigned*)(A + (mrow0 + gid + 8) * sa + k0);
        a[2] = *(const unsigned*)(A + (mrow0 + gid) * sa + k0 + 8);
        a[3] = *(const unsigned*)(A + (mrow0 + gid + 8) * sa + k0 + 8);
        const unsigned short* bp = B + (ncol0 + gid) * sb + k0;
#pragma unroll
        for (int nt = 0; nt < 4; ++nt) {
            unsigned b0 = *(const unsigned*)(bp + 8 * nt * sb);
            unsigned b1 = *(const unsigned*)(bp + 8 * nt * sb + 8);
            mma16(acc[nt], a, b0, b1);
        }
    }
}

__global__ void __launch_bounds__(NTHR, 1)
nam_kernel(const float* __restrict__ x,
           const float* __restrict__ centers,
           const float* __restrict__ logw,
           const __nv_bfloat16* __restrict__ w1t,  // [F][H1][NB]
           const __nv_bfloat16* __restrict__ w2t,  // [F][H2][H1]
           const __nv_bfloat16* __restrict__ wrt,  // [F][H2][NB]
           const float* __restrict__ b1,
           const float* __restrict__ g1,
           const float* __restrict__ be1,
           const float* __restrict__ b2,
           const float* __restrict__ g2,
           const float* __restrict__ be2,
           const float* __restrict__ br,
           const float* __restrict__ att,
           const float* __restrict__ bias,
           const float* __restrict__ Wpi,
           const float* __restrict__ bpi,
           const float* __restrict__ Wa,
           const float* __restrict__ ba,
           const float* __restrict__ Wb,
           const float* __restrict__ bb,
           float* __restrict__ out)
{
    extern __shared__ char smem[];
    unsigned short* W1T = (unsigned short*)(smem + B_W1T);
    unsigned short* W2T = (unsigned short*)(smem + B_W2T);
    unsigned short* WRT = (unsigned short*)(smem + B_WRT);
    float*  vecs = (float*)(smem + B_VEC);
    float*  w_s  = (float*)(smem + B_WSM);
    unsigned short* rbf_b  = (unsigned short*)(smem + B_SCR);
    unsigned short* hbuf_b = (unsigned short*)(smem + B_SCR);
    float2* lnred = (float2*)(smem + B_LNR);   // [row][4]
    float*  hred  = (float*)(smem + B_HRD);    // [row][4][9]

    const int tid  = threadIdx.x;
    const int lane = tid & 31;
    const int wid  = tid >> 5;
    const int gid  = lane >> 2;
    const int tidg = lane & 3;
    const int mwid = wid >> 2;      // 0..7, rows 16*mwid..+15
    const int nwid = wid & 3;       // 0..3, cols 32*nwid..+31
    const int mrow0 = 16 * mwid;
    const int ncol0 = 32 * nwid;
    const int base_row = blockIdx.x * TM;
    const int bar_id = mwid + 1;    // 128-thread group barrier

    const unsigned w1_sm = (unsigned)__cvta_generic_to_shared(W1T);
    const unsigned w2_sm = (unsigned)__cvta_generic_to_shared(W2T);
    const unsigned wr_sm = (unsigned)__cvta_generic_to_shared(WRT);

    if (tid < F) {
        float m = -1e30f;
        for (int i = 0; i < F; ++i) m = fmaxf(m, att[i]);
        float s = 0.0f;
        for (int i = 0; i < F; ++i) s += expf(att[i] - m);
        w_s[tid] = expf(att[tid] - m) / s;
    }

    float agg[4][4];
#pragma unroll
    for (int nt = 0; nt < 4; ++nt)
#pragma unroll
        for (int c = 0; c < 4; ++c) agg[nt][c] = 0.0f;

    for (int f = 0; f < F; ++f) {
        __syncthreads();

        // ---- stage pre-transposed bf16 weights (cp.async) ----
        {
            const char* s1 = (const char*)(w1t + (size_t)f * H1 * NB);
            const char* s2 = (const char*)(w2t + (size_t)f * H2 * H1);
            const char* sr = (const char*)(wrt + (size_t)f * H2 * NB);
            {   // W1t: 1024 granules, 1/thread
                int v = tid;
                cp16(w1_sm + (v >> 3) * 144 + (v & 7) * 16, s1 + v * 16);
            }
#pragma unroll
            for (int i = 0; i < 2; ++i) {   // W2t: 2048 granules
                int v = tid + i * NTHR;
                cp16(w2_sm + (v >> 4) * 272 + (v & 15) * 16, s2 + v * 16);
            }
            {   // Wrt: 1024 granules
                int v = tid;
                cp16(wr_sm + (v >> 3) * 144 + (v & 7) * 16, sr + v * 16);
            }
            asm volatile("cp.async.commit_group;");
        }
        if (tid < 128) {
            vecs[tid]         = b1 [f * H1 + tid];
            vecs[128 + tid]   = g1 [f * H1 + tid];
            vecs[256 + tid]   = be1[f * H1 + tid];
            vecs[384 + tid]   = b2 [f * H2 + tid];
            vecs[512 + tid]   = g2 [f * H2 + tid];
            vecs[640 + tid]   = be2[f * H2 + tid];
            vecs[768 + tid]   = br [f * H2 + tid];
        }

        // ---- RBF: warp (mwid,nwid) writes 4 rows of its group ----
        {
            int n0 = lane * 2;
            float c0 = __ldg(centers + f * NB + n0);
            float c1 = __ldg(centers + f * NB + n0 + 1);
            float i0 = 1.0f / (expf(clipf(__ldg(logw + f * NB + n0),     -5.0f, 5.0f)) + 0.1f);
            float i1 = 1.0f / (expf(clipf(__ldg(logw + f * NB + n0 + 1), -5.0f, 5.0f)) + 0.1f);
            int r0 = mrow0 + 4 * nwid;
#pragma unroll
            for (int rr = 0; rr < 4; ++rr) {
                int row = r0 + rr;
                float xv = clipf(__ldg(x + (size_t)(base_row + row) * F + f), -10.0f, 10.0f);
                float d0 = clipf((xv - c0) * i0, -10.0f, 10.0f);
                float d1v = clipf((xv - c1) * i1, -10.0f, 10.0f);
                float e0 = __expf(-0.5f * d0 * d0);
                float e1 = __expf(-0.5f * d1v * d1v);
                *(unsigned*)(rbf_b + row * SA_R + n0) = pack_bf2(e0, e1);
            }
        }

        asm volatile("cp.async.wait_group 0;" ::: "memory");
        __syncthreads();

        float acc[4][4];

        // ---- G3: res = rbf @ Wr^T ; fold into agg ----
#pragma unroll
        for (int nt = 0; nt < 4; ++nt)
#pragma unroll
            for (int c = 0; c < 4; ++c) acc[nt][c] = 0.0f;
        gemm16(acc, rbf_b, SA_R, WRT, SB_1, NB / 16, mrow0, ncol0, gid, tidg);
        {
            float wf01 = 0.1f * w_s[f];
#pragma unroll
            for (int nt = 0; nt < 4; ++nt) {
                int c = ncol0 + 8 * nt + 2 * tidg;
                float2 brv = *(const float2*)(vecs + 768 + c);
                agg[nt][0] += wf01 * (acc[nt][0] + brv.x);
                agg[nt][1] += wf01 * (acc[nt][1] + brv.y);
                agg[nt][2] += wf01 * (acc[nt][2] + brv.x);
                agg[nt][3] += wf01 * (acc[nt][3] + brv.y);
            }
        }

        // ---- G1: h1 = rbf @ W1^T ----
#pragma unroll
        for (int nt = 0; nt < 4; ++nt)
#pragma unroll
            for (int c = 0; c < 4; ++c) acc[nt][c] = 0.0f;
        gemm16(acc, rbf_b, SA_R, W1T, SB_1, NB / 16, mrow0, ncol0, gid, tidg);

        // ---- LN1 + gelu -> hbuf (group-scoped, 4 n-warps) ----
        {
            float sum0 = 0.f, sq0 = 0.f, sum1 = 0.f, sq1 = 0.f;
#pragma unroll
            for (int nt = 0; nt < 4; ++nt) {
                int c = ncol0 + 8 * nt + 2 * tidg;
                float2 bv = *(const float2*)(vecs + c);
                float v0 = acc[nt][0] + bv.x, v1 = acc[nt][1] + bv.y;
                float v2 = acc[nt][2] + bv.x, v3 = acc[nt][3] + bv.y;
                acc[nt][0] = v0; acc[nt][1] = v1; acc[nt][2] = v2; acc[nt][3] = v3;
                sum0 += v0 + v1; sq0 += v0 * v0 + v1 * v1;
                sum1 += v2 + v3; sq1 += v2 * v2 + v3 * v3;
            }
            sum0 = qred(sum0); sq0 = qred(sq0);
            sum1 = qred(sum1); sq1 = qred(sq1);
            int row0 = mrow0 + gid;
            if (tidg == 0) {
                lnred[row0 * 4 + nwid]       = make_float2(sum0, sq0);
                lnred[(row0 + 8) * 4 + nwid] = make_float2(sum1, sq1);
            }
            asm volatile("bar.sync %0, 128;" :: "r"(bar_id) : "memory");
            float ts0 = 0.f, tq0 = 0.f, ts1 = 0.f, tq1 = 0.f;
#pragma unroll
            for (int j = 0; j < 4; ++j) {
                float2 p0 = lnred[row0 * 4 + j];
                float2 p1 = lnred[(row0 + 8) * 4 + j];
                ts0 += p0.x; tq0 += p0.y;
                ts1 += p1.x; tq1 += p1.y;
            }
            float mu0 = ts0 * (1.0f / H1);
            float mu1 = ts1 * (1.0f / H1);
            float in0 = rsqrtf(tq0 * (1.0f / H1) - mu0 * mu0 + LN_EPS);
            float in1 = rsqrtf(tq1 * (1.0f / H1) - mu1 * mu1 + LN_EPS);
#pragma unroll
            for (int nt = 0; nt < 4; ++nt) {
                int c = ncol0 + 8 * nt + 2 * tidg;
                float2 gv  = *(const float2*)(vecs + 128 + c);
                float2 bev = *(const float2*)(vecs + 256 + c);
                float h0 = gelu_fast((acc[nt][0] - mu0) * in0 * gv.x + bev.x);
                float h1 = gelu_fast((acc[nt][1] - mu0) * in0 * gv.y + bev.y);
                float h2 = gelu_fast((acc[nt][2] - mu1) * in1 * gv.x + bev.x);
                float h3 = gelu_fast((acc[nt][3] - mu1) * in1 * gv.y + bev.y);
                *(unsigned*)(hbuf_b + row0 * SA_H + c)       = pack_bf2(h0, h1);
                *(unsigned*)(hbuf_b + (row0 + 8) * SA_H + c) = pack_bf2(h2, h3);
            }
        }
        asm volatile("bar.sync %0, 128;" :: "r"(bar_id) : "memory");

        // ---- G2: h2pre = h @ W2^T ----
#pragma unroll
        for (int nt = 0; nt < 4; ++nt)
#pragma unroll
            for (int c = 0; c < 4; ++c) acc[nt][c] = 0.0f;
        gemm16(acc, hbuf_b, SA_H, W2T, SB_2, H1 / 16, mrow0, ncol0, gid, tidg);

        // ---- LN2 + gelu; agg += wf * h2 (group-scoped) ----
        {
            float sum0 = 0.f, sq0 = 0.f, sum1 = 0.f, sq1 = 0.f;
#pragma unroll
            for (int nt = 0; nt < 4; ++nt) {
                int c = ncol0 + 8 * nt + 2 * tidg;
                float2 bv = *(const float2*)(vecs + 384 + c);
                float v0 = acc[nt][0] + bv.x, v1 = acc[nt][1] + bv.y;
                float v2 = acc[nt][2] + bv.x, v3 = acc[nt][3] + bv.y;
                acc[nt][0] = v0; acc[nt][1] = v1; acc[nt][2] = v2; acc[nt][3] = v3;
                sum0 += v0 + v1; sq0 += v0 * v0 + v1 * v1;
                sum1 += v2 + v3; sq1 += v2 * v2 + v3 * v3;
            }
            sum0 = qred(sum0); sq0 = qred(sq0);
            sum1 = qred(sum1); sq1 = qred(sq1);
            int row0 = mrow0 + gid;
            if (tidg == 0) {
                lnred[row0 * 4 + nwid]       = make_float2(sum0, sq0);
                lnred[(row0 + 8) * 4 + nwid] = make_float2(sum1, sq1);
            }
            asm volatile("bar.sync %0, 128;" :: "r"(bar_id) : "memory");
            float ts0 = 0.f, tq0 = 0.f, ts1 = 0.f, tq1 = 0.f;
#pragma unroll
            for (int j = 0; j < 4; ++j) {
                float2 p0 = lnred[row0 * 4 + j];
                float2 p1 = lnred[(row0 + 8) * 4 + j];
                ts0 += p0.x; tq0 += p0.y;
                ts1 += p1.x; tq1 += p1.y;
            }
            float mu0 = ts0 * (1.0f / H2);
            float mu1 = ts1 * (1.0f / H2);
            float in0 = rsqrtf(tq0 * (1.0f / H2) - mu0 * mu0 + LN_EPS);
            float in1 = rsqrtf(tq1 * (1.0f / H2) - mu1 * mu1 + LN_EPS);
            float wf = w_s[f];
#pragma unroll
            for (int nt = 0; nt < 4; ++nt) {
                int c = ncol0 + 8 * nt + 2 * tidg;
                float2 gv  = *(const float2*)(vecs + 512 + c);
                float2 bev = *(const float2*)(vecs + 640 + c);
                agg[nt][0] += wf * gelu_fast((acc[nt][0] - mu0) * in0 * gv.x + bev.x);
                agg[nt][1] += wf * gelu_fast((acc[nt][1] - mu0) * in0 * gv.y + bev.y);
                agg[nt][2] += wf * gelu_fast((acc[nt][2] - mu1) * in1 * gv.x + bev.x);
                agg[nt][3] += wf * gelu_fast((acc[nt][3] - mu1) * in1 * gv.y + bev.y);
            }
        }
    }

    // ---- head (exact math; hred[row][nwid][9] aliases scratch) ----
    __syncthreads();
    {
        int row0 = mrow0 + gid;
        float P[9], Q[9];
#pragma unroll
        for (int q = 0; q < 9; ++q) { P[q] = 0.f; Q[q] = 0.f; }
#pragma unroll
        for (int nt = 0; nt < 4; ++nt) {
            int c = ncol0 + 8 * nt + 2 * tidg;
            float bs0 = __ldg(bias + c), bs1 = __ldg(bias + c + 1);
            float a0 = agg[nt][0] + bs0, a1 = agg[nt][1] + bs1;
            float a2 = agg[nt][2] + bs0, a3 = agg[nt][3] + bs1;
#pragma unroll
            for (int j = 0; j < 3; ++j) {
                float wp0 = __ldg(Wpi + c * 3 + j), wp1 = __ldg(Wpi + (c + 1) * 3 + j);
                float wa0 = __ldg(Wa  + c * 3 + j), wa1 = __ldg(Wa  + (c + 1) * 3 + j);
                float wb0 = __ldg(Wb  + c * 3 + j), wb1 = __ldg(Wb  + (c + 1) * 3 + j);
                P[j]     += a0 * wp0 + a1 * wp1;  Q[j]     += a2 * wp0 + a3 * wp1;
                P[3 + j] += a0 * wa0 + a1 * wa1;  Q[3 + j] += a2 * wa0 + a3 * wa1;
                P[6 + j] += a0 * wb0 + a1 * wb1;  Q[6 + j] += a2 * wb0 + a3 * wb1;
            }
        }
#pragma unroll
        for (int q = 0; q < 9; ++q) { P[q] = qred(P[q]); Q[q] = qred(Q[q]); }

        if (tidg == 0) {
#pragma unroll
            for (int q = 0; q < 9; ++q) {
                hred[(row0 * 4 + nwid) * 9 + q]       = P[q];
                hred[((row0 + 8) * 4 + nwid) * 9 + q] = Q[q];
            }
        }
        asm volatile("bar.sync %0, 128;" :: "r"(bar_id) : "memory");
        if (nwid == 0 && tidg == 0) {
#pragma unroll
            for (int half = 0; half < 2; ++half) {
                int row = row0 + 8 * half;
                float S[9];
#pragma unroll
                for (int q = 0; q < 9; ++q) {
                    S[q] = hred[(row * 4 + 0) * 9 + q] + hred[(row * 4 + 1) * 9 + q]
                         + hred[(row * 4 + 2) * 9 + q] + hred[(row * 4 + 3) * 9 + q];
                }
                float l0 = S[0] + __ldg(bpi + 0);
                float l1 = S[1] + __ldg(bpi + 1);
                float l2 = S[2] + __ldg(bpi + 2);
                float m = fmaxf(l0, fmaxf(l1, l2));
                float e0 = expf(l0 - m), e1 = expf(l1 - m), e2 = expf(l2 - m);
                float inv_es = 1.0f / (e0 + e1 + e2);
                float ak0 = clipf(softplus_f(S[3] + __ldg(ba + 0)) + 1.01f, 1.01f, 100.0f);
                float ak1 = clipf(softplus_f(S[4] + __ldg(ba + 1)) + 1.01f, 1.01f, 100.0f);
                float ak2 = clipf(softplus_f(S[5] + __ldg(ba + 2)) + 1.01f, 1.01f, 100.0f);
                float bk0 = clipf(softplus_f(S[6] + __ldg(bb + 0)) + 1.01f, 1.01f, 100.0f);
                float bk1 = clipf(softplus_f(S[7] + __ldg(bb + 1)) + 1.01f, 1.01f, 100.0f);
                float bk2 = clipf(softplus_f(S[8] + __ldg(bb + 2)) + 1.01f, 1.01f, 100.0f);
                float pred = (e0 * inv_es) * (ak0 / (ak0 + bk0))
                           + (e1 * inv_es) * (ak1 / (ak1 + bk1))
                           + (e2 * inv_es) * (ak2 / (ak2 + bk2));
                out[base_row + row] = clipf(pred, 0.001f, 0.999f);
            }
        }
    }
}

extern "C" void kernel_launch(void* const* d_in, const int* in_sizes, int n_in,
                              void* d_out, int out_size) {
    (void)in_sizes; (void)n_in; (void)out_size;
    cudaFuncSetAttribute(nam_kernel,
                         cudaFuncAttributeMaxDynamicSharedMemorySize, SMEM_BYTES);
    const float* x       = (const float*)d_in[0];
    const float* centers = (const float*)d_in[1];
    const float* logw    = (const float*)d_in[2];
    const float* W1      = (const float*)d_in[3];
    const float* b1      = (const float*)d_in[4];
    const float* g1      = (const float*)d_in[5];
    const float* be1     = (const float*)d_in[6];
    const float* W2      = (const float*)d_in[7];
    const float* b2      = (const float*)d_in[8];
    const float* g2      = (const float*)d_in[9];
    const float* be2     = (const float*)d_in[10];
    const float* Wr      = (const float*)d_in[11];
    const float* br      = (const float*)d_in[12];
    const float* att     = (const float*)d_in[13];
    const float* bias    = (const float*)d_in[14];
    const float* Wpi     = (const float*)d_in[15];
    const float* bpi     = (const float*)d_in[16];
    const float* Wa      = (const float*)d_in[17];
    const float* ba      = (const float*)d_in[18];
    const float* Wb      = (const float*)d_in[19];
    const float* bb      = (const float*)d_in[20];
    float* out = (float*)d_out;

    void *p1, *p2, *p3;
    cudaGetSymbolAddress(&p1, g_w1t);
    cudaGetSymbolAddress(&p2, g_w2t);
    cudaGetSymbolAddress(&p3, g_wrt);

    transpose_prep<<<F * (H1 / 64), 256>>>(W1, (__nv_bfloat16*)p1, NB, H1);
    transpose_prep<<<F * (H2 / 64), 256>>>(W2, (__nv_bfloat16*)p2, H1, H2);
    transpose_prep<<<F * (H2 / 64), 256>>>(Wr, (__nv_bfloat16*)p3, NB, H2);

    nam_kernel<<<B_TOT / TM, NTHR, SMEM_BYTES>>>(
        x, centers, logw,
        (const __nv_bfloat16*)p1, (const __nv_bfloat16*)p2, (const __nv_bfloat16*)p3,
        b1, g1, be1, b2, g2, be2, br,
        att, bias, Wpi, bpi, Wa, ba, Wb, bb, out);
}